// round 15
// baseline (speedup 1.0000x reference)
#include <cuda_runtime.h>
#include <math.h>

namespace {

constexpr int BQ   = 256;
constexpr int NSV  = 64;
constexpr int NTRK = 512;
constexpr int H    = 32;
constexpr unsigned FULL = 0xffffffffu;
typedef unsigned long long u64;

// ---------------- scratch (static device globals; no allocation) ----------------
__device__ float g_enc_sv [BQ * NSV  * H];
__device__ float g_enc_trk[BQ * NTRK * H];
__device__ float g_enc_pfc[BQ * NTRK * H];
__device__ float g_f1[BQ * NTRK * H];
__device__ float g_f2[BQ * NTRK * H];
__device__ float g_P_sv [BQ * NSV  * H];   // enc_sv  @ Wb
__device__ float g_P_pfc[BQ * NTRK * H];   // enc_pfc @ Wb
__device__ float g_P_f1 [BQ * NTRK * H];   // f1      @ Wb
__device__ float g_A_trk[BQ * NTRK * H];   // enc_trk @ Wd + b
__device__ float g_A_f2 [BQ * NTRK * H];   // f2      @ Wd + b

__device__ __forceinline__ float elu_f(float x) {
    return x > 0.f ? x : (__expf(x) - 1.f);
}

// monotone float -> sortable uint
__device__ __forceinline__ unsigned sortable_u(float v) {
    unsigned u = __float_as_uint(v);
    return (u & 0x80000000u) ? ~u : (u | 0x80000000u);
}

// packed fp32x2 helpers (Blackwell)
__device__ __forceinline__ u64 pack2_dup(float v) {
    u64 r; asm("mov.b64 %0, {%1, %1};" : "=l"(r) : "f"(v)); return r;
}
__device__ __forceinline__ u64 fma2(u64 a, u64 b, u64 c) {
    u64 d; asm("fma.rn.f32x2 %0, %1, %2, %3;" : "=l"(d) : "l"(a), "l"(b), "l"(c)); return d;
}
__device__ __forceinline__ float2 unpack2(u64 v) {
    float2 f; asm("mov.b64 {%0, %1}, %2;" : "=f"(f.x), "=f"(f.y) : "l"(v)); return f;
}

// ---------------- encoder + fused node projection (smem weights, low regs) ----------------
template<int FIN, int MODE>
__device__ __forceinline__ void encode_proj_body(
    const float* __restrict__ x,
    const float* __restrict__ b1, const float* __restrict__ b2,
    const float* __restrict__ conv_b,
    float* __restrict__ out, float* __restrict__ projOut, int blk,
    float (*shX)[120], float (*shH)[4][32],
    const float* shW1, const float* shW2, const float* shWp)
{
    int tid = threadIdx.x, lane = tid & 31, w = tid >> 5;

    const float bb1 = b1[lane], bb2 = b2[lane];
    const float bp  = MODE ? conv_b[lane] : 0.f;

    int base = (blk * 8 + w) * 16;
#pragma unroll
    for (int it = 0; it < 4; it++) {
        int n0 = base + it * 4;
        for (int i = lane; i < 4 * FIN; i += 32) shX[w][i] = x[n0 * FIN + i];
        __syncwarp();
        float h[4] = {bb1, bb1, bb1, bb1};
#pragma unroll
        for (int i = 0; i < FIN; i++) {
            float wv = shW1[i * 32 + lane];
#pragma unroll
            for (int u = 0; u < 4; u++)
                h[u] = fmaf(shX[w][u * FIN + i], wv, h[u]);
        }
#pragma unroll
        for (int u = 0; u < 4; u++) { h[u] = elu_f(h[u]); shH[w][u][lane] = h[u]; }
        __syncwarp();
        float y[4] = {bb2, bb2, bb2, bb2};
#pragma unroll
        for (int i = 0; i < 32; i++) {
            float wv = shW2[i * 32 + lane];
#pragma unroll
            for (int u = 0; u < 4; u++)
                y[u] = fmaf(shH[w][u][i], wv, y[u]);
        }
        __syncwarp();
#pragma unroll
        for (int u = 0; u < 4; u++) {
            float yv = elu_f(y[u]);
            out[(n0 + u) * 32 + lane] = yv;
            shH[w][u][lane] = yv;
        }
        __syncwarp();
        float p[4] = {bp, bp, bp, bp};
#pragma unroll
        for (int i = 0; i < 32; i++) {
            float wv = shWp[i * 32 + lane];
#pragma unroll
            for (int u = 0; u < 4; u++)
                p[u] = fmaf(shH[w][u][i], wv, p[u]);
        }
#pragma unroll
        for (int u = 0; u < 4; u++) projOut[(n0 + u) * 32 + lane] = p[u];
        __syncwarp();
    }
}

// merged encoder+proj1
__global__ void __launch_bounds__(256, 6) encode_all_k(
    const float* __restrict__ x_trk, const float* __restrict__ tW1, const float* __restrict__ tb1,
    const float* __restrict__ tW2, const float* __restrict__ tb2,
    const float* __restrict__ x_pfc, const float* __restrict__ pW1, const float* __restrict__ pb1,
    const float* __restrict__ pW2, const float* __restrict__ pb2,
    const float* __restrict__ x_sv, const float* __restrict__ sW1, const float* __restrict__ sb1,
    const float* __restrict__ sW2, const float* __restrict__ sb2,
    const float* __restrict__ conv_W, const float* __restrict__ conv_b,
    float* __restrict__ enc_trk, float* __restrict__ enc_pfc, float* __restrict__ enc_sv,
    float* __restrict__ A_trk, float* __restrict__ P_pfc, float* __restrict__ P_sv)
{
    __shared__ float shX[8][120];
    __shared__ float shH[8][4][32];
    __shared__ float shW1[960];
    __shared__ float shW2[1024];
    __shared__ float shWp[1024];
    int b = blockIdx.x;
    const float* W1 = (b < 1024) ? tW1 : (b < 2048) ? pW1 : sW1;
    const float* W2 = (b < 1024) ? tW2 : (b < 2048) ? pW2 : sW2;
    const int fin   = (b < 1024) ? 30 : (b < 2048) ? 10 : 14;
    for (int i = threadIdx.x; i < fin * 32; i += 256) shW1[i] = W1[i];
    for (int i = threadIdx.x; i < 1024; i += 256) shW2[i] = W2[i];
    if (b < 1024) {
        for (int i = threadIdx.x; i < 1024; i += 256)
            shWp[i] = conv_W[i] - conv_W[1024 + i];         // Wd
    } else {
        for (int i = threadIdx.x; i < 1024; i += 256)
            shWp[i] = conv_W[1024 + i];                     // Wb
    }
    __syncthreads();
    if (b < 1024)
        encode_proj_body<30,1>(x_trk, tb1, tb2, conv_b, enc_trk, A_trk, b, shX, shH, shW1, shW2, shWp);
    else if (b < 2048)
        encode_proj_body<10,0>(x_pfc, pb1, pb2, conv_b, enc_pfc, P_pfc, b - 1024, shX, shH, shW1, shW2, shWp);
    else
        encode_proj_body<14,0>(x_sv, sb1, sb2, conv_b, enc_sv, P_sv, b - 2048, shX, shH, shW1, shW2, shWp);
}

// ---------------- smem layout for conv kernels (floats) ----------------
constexpr int NW     = 20;            // warps per conv block (640 threads)
constexpr int OF_P    = 16512;
constexpr int OF_NORM = 32896;
constexpr int OF_W    = 33408;
constexpr int OF_S    = 34432;
constexpr int SMEM_F1F2 = (OF_S + NW * 4 * 32) * 4;   // 147968 B
constexpr int SMEM_F3   = (OF_W + NW * 32) * 4;       // 136192 B

// tree argmin over 16 keys: smallest key; ties -> smallest t.
__device__ __forceinline__ void argmin16(const unsigned* ka, unsigned& bk, int& bt)
{
    unsigned tk[8]; int tt[8];
#pragma unroll
    for (int i = 0; i < 8; i++) {
        bool le = ka[2*i] <= ka[2*i+1];
        tk[i] = le ? ka[2*i] : ka[2*i+1];
        tt[i] = le ? 2*i : 2*i+1;
    }
#pragma unroll
    for (int i = 0; i < 4; i++) {
        bool le = tk[2*i] <= tk[2*i+1];
        tk[i] = le ? tk[2*i] : tk[2*i+1];
        tt[i] = le ? tt[2*i] : tt[2*i+1];
    }
#pragma unroll
    for (int i = 0; i < 2; i++) {
        bool le = tk[2*i] <= tk[2*i+1];
        tk[i] = le ? tk[2*i] : tk[2*i+1];
        tt[i] = le ? tt[2*i] : tt[2*i+1];
    }
    bool le = tk[0] <= tk[1];
    bk = le ? tk[0] : tk[1];
    bt = le ? tt[0] : tt[1];
}

// ---------------- edge conv NS=512, u=4 dst per warp ----------------
// EPI=0 : write outB (=f2) + projB (= f2@Wd + conv_b)
// EPI=1 : mean-pool + MLP head + sigmoid into outF
// 640 threads = 20 warps, 4 dst per pass, 7 rounds (last partial).
template<int EPI>
__device__ void conv512_body(
    const float* __restrict__ srcB, const float* __restrict__ dstB,
    const float* __restrict__ PB,   const float* __restrict__ AB,
    float* __restrict__ outB, float* __restrict__ projB,
    const float* __restrict__ conv_W, const float* __restrict__ conv_b,
    const float* __restrict__ oW1, const float* __restrict__ ob1,
    const float* __restrict__ oW2, const float* __restrict__ ob2,
    float* __restrict__ outF, int ev, int out_size,
    float* sh)
{
    float* shT    = sh;
    float* shP    = sh + OF_P;
    float* shNorm = sh + OF_NORM;
    float* shW    = sh + OF_W;       // EPI0: Wd ; EPI1: pool partials
    float* shS    = sh + OF_S;       // EPI0: per-warp staging

    const int tid  = threadIdx.x;
    const int lane = tid & 31;
    const int w    = tid >> 5;           // 0..19

    if (EPI == 0) {
        for (int i = tid; i < 1024; i += 32 * NW)
            shW[i] = conv_W[i] - conv_W[1024 + i];   // Wd
    }
    for (int r = w; r < 512; r += NW) {
        float v = srcB[r * 32 + lane];
        shT[lane * 516 + r] = v;
        shP[r * 32 + lane] = PB[r * 32 + lane];
        float s2 = v * v;
#pragma unroll
        for (int o = 16; o; o >>= 1) s2 += __shfl_xor_sync(FULL, s2, o);
        if (lane == 0) shNorm[r] = s2;
    }
    __syncthreads();

    const float cb = (EPI == 0) ? conv_b[lane] : 0.f;
    float sumv = 0.f;   // EPI1 pooling accumulator (dim = lane)

    for (int pass = 0; pass < 7; pass++) {
        const int g0 = pass * NW + w;
        if (g0 >= 128) break;           // uniform per warp
        const int d0 = g0 * 4;

        float xr[4];
#pragma unroll
        for (int u = 0; u < 4; u++) xr[u] = dstB[(d0 + u) * 32 + lane];

        // ---- packed f32x2 distance accumulation (each LDS feeds 4 dst) ----
        u64 acc2[4][8];
#pragma unroll
        for (int u = 0; u < 4; u++)
#pragma unroll
            for (int p = 0; p < 8; p++) acc2[u][p] = 0ull;

#pragma unroll 4
        for (int d = 0; d < 32; d++) {
            u64 xp0 = pack2_dup(__shfl_sync(FULL, xr[0], d));
            u64 xp1 = pack2_dup(__shfl_sync(FULL, xr[1], d));
            u64 xp2 = pack2_dup(__shfl_sync(FULL, xr[2], d));
            u64 xp3 = pack2_dup(__shfl_sync(FULL, xr[3], d));
            const float* base = &shT[d * 516 + 4 * lane];
#pragma unroll
            for (int tp = 0; tp < 4; tp++) {
                ulonglong2 vv = *(const ulonglong2*)(base + 128 * tp);
                acc2[0][2*tp  ] = fma2(xp0, vv.x, acc2[0][2*tp  ]);
                acc2[0][2*tp+1] = fma2(xp0, vv.y, acc2[0][2*tp+1]);
                acc2[1][2*tp  ] = fma2(xp1, vv.x, acc2[1][2*tp  ]);
                acc2[1][2*tp+1] = fma2(xp1, vv.y, acc2[1][2*tp+1]);
                acc2[2][2*tp  ] = fma2(xp2, vv.x, acc2[2][2*tp  ]);
                acc2[2][2*tp+1] = fma2(xp2, vv.y, acc2[2][2*tp+1]);
                acc2[3][2*tp  ] = fma2(xp3, vv.x, acc2[3][2*tp  ]);
                acc2[3][2*tp+1] = fma2(xp3, vv.y, acc2[3][2*tp+1]);
            }
        }

        // keys: rv = ||s||^2 - 2<d,s>  (rank-equivalent to d2)
        // converted per-u so acc2[u] dies as karr[u] is born (reg-peak control)
        unsigned karr[4][16];
#pragma unroll
        for (int u = 0; u < 4; u++) {
#pragma unroll
            for (int tp = 0; tp < 4; tp++) {
#pragma unroll
                for (int hh = 0; hh < 2; hh++) {
                    int s0 = 4 * lane + 128 * tp + 2 * hh;
                    float2 nv = *(const float2*)&shNorm[s0];
                    int t0 = 4 * tp + 2 * hh;
                    float2 f = unpack2(acc2[u][2 * tp + hh]);
                    karr[u][t0    ] = sortable_u(fmaf(-2.f, f.x, nv.x));
                    karr[u][t0 + 1] = sortable_u(fmaf(-2.f, f.y, nv.y));
                }
            }
        }

        float a[4];
#pragma unroll
        for (int u = 0; u < 4; u++) a[u] = AB[(d0 + u) * 32 + lane];

        // ---- top-8: 4 interleaved chains, inline gather (no nb arrays) ----
        float m[4] = {-3.0e38f, -3.0e38f, -3.0e38f, -3.0e38f};
#pragma unroll
        for (int k = 0; k < 8; k++) {
#pragma unroll
            for (int u = 0; u < 4; u++) {
                unsigned bk; int bt;
                argmin16(karr[u], bk, bt);
                unsigned gk = __reduce_min_sync(FULL, bk);
                int s = 4 * lane + 128 * (bt >> 2) + (bt & 3);
                unsigned cand = (bk == gk) ? (unsigned)s : 0xFFFFFFFFu;
                unsigned gi = __reduce_min_sync(FULL, cand);
                bool won = (bk == gk) && ((unsigned)s == gi);
#pragma unroll
                for (int t = 0; t < 16; t++)
                    karr[u][t] = (won && t == bt) ? 0xFFFFFFFFu : karr[u][t];
                float pj = shP[gi * 32 + lane];   // broadcast row, conflict-free
                m[u] = fmaxf(m[u], elu_f(a[u] + pj));
            }
        }

        if (EPI == 0) {
#pragma unroll
            for (int u = 0; u < 4; u++) {
                outB[(d0 + u) * 32 + lane] = m[u];
                shS[(w * 4 + u) * 32 + lane] = m[u];
            }
            __syncwarp();
            float p[4] = {cb, cb, cb, cb};
#pragma unroll
            for (int i = 0; i < 32; i++) {
                float wv = shW[i * 32 + lane];
#pragma unroll
                for (int u = 0; u < 4; u++)
                    p[u] = fmaf(shS[(w * 4 + u) * 32 + i], wv, p[u]);
            }
#pragma unroll
            for (int u = 0; u < 4; u++) projB[(d0 + u) * 32 + lane] = p[u];
            __syncwarp();
        } else {
            sumv += (m[0] + m[1]) + (m[2] + m[3]);
        }
    }

    if (EPI == 1) {
        // mean pool over 512 dst + output MLP + sigmoid
        shW[w * 32 + lane] = sumv;   // reuse shW region as pool partials
        __syncthreads();
        if (w == 0) {
            float p = 0.f;
#pragma unroll
            for (int i = 0; i < NW; i++) p += shW[i * 32 + lane];
            p *= (1.f / 512.f);
            float h = ob1[lane];
#pragma unroll
            for (int i = 0; i < 32; i++)
                h = fmaf(__shfl_sync(FULL, p, i), oW1[i * 32 + lane], h);
            h = elu_f(h);
            float z = h * oW2[lane];
#pragma unroll
            for (int o = 16; o; o >>= 1) z += __shfl_xor_sync(FULL, z, o);
            if (lane == 0) {
                float t = z + ob2[0];
                outF[ev] = 1.f / (1.f + __expf(-t));
                if (out_size == 768)
                    ((long long*)(outF + 256))[ev] = (long long)ev;
                else if (out_size > 256 && ev < out_size - 256)
                    outF[256 + ev] = (float)ev;
            }
        }
    }
}

// ---------------- edge conv NS=64 (sv -> trk): u=4, fused proj P_f1 = m@Wb ----------------
__device__ void conv64_body(
    const float* __restrict__ srcB, const float* __restrict__ dstB,
    const float* __restrict__ PB,   const float* __restrict__ AB,
    float* __restrict__ outB, float* __restrict__ projB,
    const float* __restrict__ conv_W,
    float* sh)
{
    constexpr int TS = 65;
    float* shT    = sh;                // [32][65]
    float* shP    = sh + OF_P;         // [64][32]
    float* shNorm = sh + OF_NORM;      // [64]
    float* shW    = sh + OF_W;         // Wb
    float* shS    = sh + OF_S;         // [NW][4][32]

    const int tid  = threadIdx.x;
    const int lane = tid & 31;
    const int w    = tid >> 5;         // 0..19

    for (int i = tid; i < 1024; i += 32 * NW) shW[i] = conv_W[1024 + i];  // Wb
    for (int r = w; r < 64; r += NW) {
        float v = srcB[r * 32 + lane];
        shT[lane * TS + r] = v;
        shP[r * 32 + lane] = PB[r * 32 + lane];
        float s2 = v * v;
#pragma unroll
        for (int o = 16; o; o >>= 1) s2 += __shfl_xor_sync(FULL, s2, o);
        if (lane == 0) shNorm[r] = s2;
    }
    __syncthreads();

    // 128 groups of 4 dst; warp-strided
    for (int g0 = w; g0 < 128; g0 += NW) {
        const int d0 = g0 * 4;

        float xr[4], a[4];
#pragma unroll
        for (int u = 0; u < 4; u++) {
            xr[u] = dstB[(d0 + u) * 32 + lane];
            a[u]  = AB  [(d0 + u) * 32 + lane];
        }

        float acc[4][2];
#pragma unroll
        for (int u = 0; u < 4; u++) { acc[u][0] = 0.f; acc[u][1] = 0.f; }
#pragma unroll 4
        for (int d = 0; d < 32; d++) {
            float xd0 = __shfl_sync(FULL, xr[0], d);
            float xd1 = __shfl_sync(FULL, xr[1], d);
            float xd2 = __shfl_sync(FULL, xr[2], d);
            float xd3 = __shfl_sync(FULL, xr[3], d);
#pragma unroll
            for (int t = 0; t < 2; t++) {
                float v = shT[d * TS + lane + 32 * t];
                acc[0][t] = fmaf(xd0, v, acc[0][t]);
                acc[1][t] = fmaf(xd1, v, acc[1][t]);
                acc[2][t] = fmaf(xd2, v, acc[2][t]);
                acc[3][t] = fmaf(xd3, v, acc[3][t]);
            }
        }
        unsigned karr[4][2];
#pragma unroll
        for (int t = 0; t < 2; t++) {
            float nv = shNorm[lane + 32 * t];
#pragma unroll
            for (int u = 0; u < 4; u++)
                karr[u][t] = sortable_u(fmaf(-2.f, acc[u][t], nv));
        }

        int nb[4][8];
#pragma unroll
        for (int k = 0; k < 8; k++) {
#pragma unroll
            for (int u = 0; u < 4; u++) {
                bool le = karr[u][0] <= karr[u][1];
                unsigned bk = le ? karr[u][0] : karr[u][1];
                int bt = le ? 0 : 1;
                unsigned gk = __reduce_min_sync(FULL, bk);
                int s = lane + 32 * bt;
                unsigned cand = (bk == gk) ? (unsigned)s : 0xFFFFFFFFu;
                unsigned gi = __reduce_min_sync(FULL, cand);
                bool won = (bk == gk) && ((unsigned)s == gi);
#pragma unroll
                for (int t = 0; t < 2; t++)
                    karr[u][t] = (won && t == bt) ? 0xFFFFFFFFu : karr[u][t];
                nb[u][k] = (int)gi;
            }
        }

        float m[4] = {-3.0e38f, -3.0e38f, -3.0e38f, -3.0e38f};
#pragma unroll
        for (int k = 0; k < 8; k++) {
#pragma unroll
            for (int u = 0; u < 4; u++) {
                float pj = shP[nb[u][k] * 32 + lane];
                m[u] = fmaxf(m[u], elu_f(a[u] + pj));
            }
        }

        // write f1 + fused proj P_f1 = m @ Wb
#pragma unroll
        for (int u = 0; u < 4; u++) {
            outB[(d0 + u) * 32 + lane] = m[u];
            shS[(w * 4 + u) * 32 + lane] = m[u];
        }
        __syncwarp();
        float p[4] = {0.f, 0.f, 0.f, 0.f};
#pragma unroll
        for (int i = 0; i < 32; i++) {
            float wv = shW[i * 32 + lane];
#pragma unroll
            for (int u = 0; u < 4; u++)
                p[u] = fmaf(shS[(w * 4 + u) * 32 + i], wv, p[u]);
        }
#pragma unroll
        for (int u = 0; u < 4; u++) projB[(d0 + u) * 32 + lane] = p[u];
        __syncwarp();
    }
}

// merged conv for f1 (sv->trk, NS=64, +P_f1) and f2 (pfc->trk, NS=512, +A_f2).
// Interleaved block order: even blocks = f2 (long), odd = f1 (short) for wave mixing.
__global__ void __launch_bounds__(32 * NW, 1) conv_f1f2_k(
    const float* __restrict__ enc_sv,  const float* __restrict__ enc_pfc,
    const float* __restrict__ enc_trk,
    const float* __restrict__ P_sv,    const float* __restrict__ P_pfc,
    const float* __restrict__ A_trk,
    const float* __restrict__ conv_W,  const float* __restrict__ conv_b,
    float* __restrict__ f1, float* __restrict__ f2,
    float* __restrict__ P_f1, float* __restrict__ A_f2)
{
    extern __shared__ float sh[];
    int b = blockIdx.x;
    int e = b >> 1;
    if ((b & 1) == 0) {
        conv512_body<0>(enc_pfc + (size_t)e * 512 * 32,
                        enc_trk + (size_t)e * 512 * 32,
                        P_pfc   + (size_t)e * 512 * 32,
                        A_trk   + (size_t)e * 512 * 32,
                        f2      + (size_t)e * 512 * 32,
                        A_f2    + (size_t)e * 512 * 32,
                        conv_W, conv_b,
                        nullptr, nullptr, nullptr, nullptr, nullptr, 0, 0, sh);
    } else {
        conv64_body(enc_sv  + (size_t)e * 64  * 32,
                    enc_trk + (size_t)e * 512 * 32,
                    P_sv    + (size_t)e * 64  * 32,
                    A_trk   + (size_t)e * 512 * 32,
                    f1      + (size_t)e * 512 * 32,
                    P_f1    + (size_t)e * 512 * 32,
                    conv_W, sh);
    }
}

// conv f3 + fused mean-pool + output MLP + sigmoid (+ arange tail)
__global__ void __launch_bounds__(32 * NW, 1) conv_f3_k(
    const float* __restrict__ f1, const float* __restrict__ f2,
    const float* __restrict__ P_f1, const float* __restrict__ A_f2,
    const float* __restrict__ oW1, const float* __restrict__ ob1,
    const float* __restrict__ oW2, const float* __restrict__ ob2,
    float* __restrict__ outF, int out_size)
{
    extern __shared__ float sh[];
    int b = blockIdx.x;
    conv512_body<1>(f1   + (size_t)b * 512 * 32,
                    f2   + (size_t)b * 512 * 32,
                    P_f1 + (size_t)b * 512 * 32,
                    A_f2 + (size_t)b * 512 * 32,
                    nullptr, nullptr, nullptr, nullptr,
                    oW1, ob1, oW2, ob2, outF, b, out_size, sh);
}

} // namespace

extern "C" void kernel_launch(void* const* d_in, const int* in_sizes, int n_in,
                              void* d_out, int out_size)
{
    const float* x_sv   = (const float*)d_in[0];
    const float* x_trk  = (const float*)d_in[1];
    const float* x_pfc  = (const float*)d_in[2];
    // d_in[3..5] = batch indices (implicit, unused)
    const float* sv_W1  = (const float*)d_in[6];
    const float* sv_b1  = (const float*)d_in[7];
    const float* sv_W2  = (const float*)d_in[8];
    const float* sv_b2  = (const float*)d_in[9];
    const float* trk_W1 = (const float*)d_in[10];
    const float* trk_b1 = (const float*)d_in[11];
    const float* trk_W2 = (const float*)d_in[12];
    const float* trk_b2 = (const float*)d_in[13];
    const float* pfc_W1 = (const float*)d_in[14];
    const float* pfc_b1 = (const float*)d_in[15];
    const float* pfc_W2 = (const float*)d_in[16];
    const float* pfc_b2 = (const float*)d_in[17];
    const float* conv_W = (const float*)d_in[18];
    const float* conv_b = (const float*)d_in[19];
    const float* out_W1 = (const float*)d_in[20];
    const float* out_b1 = (const float*)d_in[21];
    const float* out_W2 = (const float*)d_in[22];
    const float* out_b2 = (const float*)d_in[23];

    float *enc_sv, *enc_trk, *enc_pfc, *f1, *f2;
    float *P_sv, *P_pfc, *P_f1, *A_trk, *A_f2;
    cudaGetSymbolAddress((void**)&enc_sv,  g_enc_sv);
    cudaGetSymbolAddress((void**)&enc_trk, g_enc_trk);
    cudaGetSymbolAddress((void**)&enc_pfc, g_enc_pfc);
    cudaGetSymbolAddress((void**)&f1, g_f1);
    cudaGetSymbolAddress((void**)&f2, g_f2);
    cudaGetSymbolAddress((void**)&P_sv,  g_P_sv);
    cudaGetSymbolAddress((void**)&P_pfc, g_P_pfc);
    cudaGetSymbolAddress((void**)&P_f1,  g_P_f1);
    cudaGetSymbolAddress((void**)&A_trk, g_A_trk);
    cudaGetSymbolAddress((void**)&A_f2,  g_A_f2);

    cudaFuncSetAttribute(conv_f1f2_k,
                         cudaFuncAttributeMaxDynamicSharedMemorySize, SMEM_F1F2);
    cudaFuncSetAttribute(conv_f3_k,
                         cudaFuncAttributeMaxDynamicSharedMemorySize, SMEM_F3);

    encode_all_k<<<2176, 256>>>(
        x_trk, trk_W1, trk_b1, trk_W2, trk_b2,
        x_pfc, pfc_W1, pfc_b1, pfc_W2, pfc_b2,
        x_sv,  sv_W1,  sv_b1,  sv_W2,  sv_b2,
        conv_W, conv_b,
        enc_trk, enc_pfc, enc_sv, A_trk, P_pfc, P_sv);

    conv_f1f2_k<<<512, 32 * NW, SMEM_F1F2>>>(enc_sv, enc_pfc, enc_trk,
                                             P_sv, P_pfc, A_trk,
                                             conv_W, conv_b,
                                             f1, f2, P_f1, A_f2);

    conv_f3_k<<<BQ, 32 * NW, SMEM_F3>>>(f1, f2, P_f1, A_f2,
                                        out_W1, out_b1, out_W2, out_b2,
                                        (float*)d_out, out_size);
}

// round 16
// speedup vs baseline: 1.4725x; 1.4725x over previous
#include <cuda_runtime.h>
#include <math.h>

namespace {

constexpr int BQ   = 256;
constexpr int NSV  = 64;
constexpr int NTRK = 512;
constexpr int H    = 32;
constexpr unsigned FULL = 0xffffffffu;
typedef unsigned long long u64;

// ---------------- scratch (static device globals; no allocation) ----------------
__device__ float g_enc_sv [BQ * NSV  * H];
__device__ float g_enc_trk[BQ * NTRK * H];
__device__ float g_enc_pfc[BQ * NTRK * H];
__device__ float g_f1[BQ * NTRK * H];
__device__ float g_f2[BQ * NTRK * H];
__device__ float g_P_sv [BQ * NSV  * H];   // enc_sv  @ Wb
__device__ float g_P_pfc[BQ * NTRK * H];   // enc_pfc @ Wb
__device__ float g_P_f1 [BQ * NTRK * H];   // f1      @ Wb
__device__ float g_A_trk[BQ * NTRK * H];   // enc_trk @ Wd + b
__device__ float g_A_f2 [BQ * NTRK * H];   // f2      @ Wd + b

__device__ __forceinline__ float elu_f(float x) {
    return x > 0.f ? x : (__expf(x) - 1.f);
}

// monotone float -> sortable uint
__device__ __forceinline__ unsigned sortable_u(float v) {
    unsigned u = __float_as_uint(v);
    return (u & 0x80000000u) ? ~u : (u | 0x80000000u);
}

// packed fp32x2 helpers (Blackwell)
__device__ __forceinline__ u64 pack2_dup(float v) {
    u64 r; asm("mov.b64 %0, {%1, %1};" : "=l"(r) : "f"(v)); return r;
}
__device__ __forceinline__ u64 fma2(u64 a, u64 b, u64 c) {
    u64 d; asm("fma.rn.f32x2 %0, %1, %2, %3;" : "=l"(d) : "l"(a), "l"(b), "l"(c)); return d;
}
__device__ __forceinline__ float2 unpack2(u64 v) {
    float2 f; asm("mov.b64 {%0, %1}, %2;" : "=f"(f.x), "=f"(f.y) : "l"(v)); return f;
}

// ---------------- encoder + fused node projection (smem weights, low regs) ----------------
template<int FIN, int MODE>
__device__ __forceinline__ void encode_proj_body(
    const float* __restrict__ x,
    const float* __restrict__ b1, const float* __restrict__ b2,
    const float* __restrict__ conv_b,
    float* __restrict__ out, float* __restrict__ projOut, int blk,
    float (*shX)[120], float (*shH)[4][32],
    const float* shW1, const float* shW2, const float* shWp)
{
    int tid = threadIdx.x, lane = tid & 31, w = tid >> 5;

    const float bb1 = b1[lane], bb2 = b2[lane];
    const float bp  = MODE ? conv_b[lane] : 0.f;

    int base = (blk * 8 + w) * 16;
#pragma unroll
    for (int it = 0; it < 4; it++) {
        int n0 = base + it * 4;
        for (int i = lane; i < 4 * FIN; i += 32) shX[w][i] = x[n0 * FIN + i];
        __syncwarp();
        float h[4] = {bb1, bb1, bb1, bb1};
#pragma unroll
        for (int i = 0; i < FIN; i++) {
            float wv = shW1[i * 32 + lane];
#pragma unroll
            for (int u = 0; u < 4; u++)
                h[u] = fmaf(shX[w][u * FIN + i], wv, h[u]);
        }
#pragma unroll
        for (int u = 0; u < 4; u++) { h[u] = elu_f(h[u]); shH[w][u][lane] = h[u]; }
        __syncwarp();
        float y[4] = {bb2, bb2, bb2, bb2};
#pragma unroll
        for (int i = 0; i < 32; i++) {
            float wv = shW2[i * 32 + lane];
#pragma unroll
            for (int u = 0; u < 4; u++)
                y[u] = fmaf(shH[w][u][i], wv, y[u]);
        }
        __syncwarp();
#pragma unroll
        for (int u = 0; u < 4; u++) {
            float yv = elu_f(y[u]);
            out[(n0 + u) * 32 + lane] = yv;
            shH[w][u][lane] = yv;
        }
        __syncwarp();
        float p[4] = {bp, bp, bp, bp};
#pragma unroll
        for (int i = 0; i < 32; i++) {
            float wv = shWp[i * 32 + lane];
#pragma unroll
            for (int u = 0; u < 4; u++)
                p[u] = fmaf(shH[w][u][i], wv, p[u]);
        }
#pragma unroll
        for (int u = 0; u < 4; u++) projOut[(n0 + u) * 32 + lane] = p[u];
        __syncwarp();
    }
}

// merged encoder+proj1
__global__ void __launch_bounds__(256, 6) encode_all_k(
    const float* __restrict__ x_trk, const float* __restrict__ tW1, const float* __restrict__ tb1,
    const float* __restrict__ tW2, const float* __restrict__ tb2,
    const float* __restrict__ x_pfc, const float* __restrict__ pW1, const float* __restrict__ pb1,
    const float* __restrict__ pW2, const float* __restrict__ pb2,
    const float* __restrict__ x_sv, const float* __restrict__ sW1, const float* __restrict__ sb1,
    const float* __restrict__ sW2, const float* __restrict__ sb2,
    const float* __restrict__ conv_W, const float* __restrict__ conv_b,
    float* __restrict__ enc_trk, float* __restrict__ enc_pfc, float* __restrict__ enc_sv,
    float* __restrict__ A_trk, float* __restrict__ P_pfc, float* __restrict__ P_sv)
{
    __shared__ float shX[8][120];
    __shared__ float shH[8][4][32];
    __shared__ float shW1[960];
    __shared__ float shW2[1024];
    __shared__ float shWp[1024];
    int b = blockIdx.x;
    const float* W1 = (b < 1024) ? tW1 : (b < 2048) ? pW1 : sW1;
    const float* W2 = (b < 1024) ? tW2 : (b < 2048) ? pW2 : sW2;
    const int fin   = (b < 1024) ? 30 : (b < 2048) ? 10 : 14;
    for (int i = threadIdx.x; i < fin * 32; i += 256) shW1[i] = W1[i];
    for (int i = threadIdx.x; i < 1024; i += 256) shW2[i] = W2[i];
    if (b < 1024) {
        for (int i = threadIdx.x; i < 1024; i += 256)
            shWp[i] = conv_W[i] - conv_W[1024 + i];         // Wd
    } else {
        for (int i = threadIdx.x; i < 1024; i += 256)
            shWp[i] = conv_W[1024 + i];                     // Wb
    }
    __syncthreads();
    if (b < 1024)
        encode_proj_body<30,1>(x_trk, tb1, tb2, conv_b, enc_trk, A_trk, b, shX, shH, shW1, shW2, shWp);
    else if (b < 2048)
        encode_proj_body<10,0>(x_pfc, pb1, pb2, conv_b, enc_pfc, P_pfc, b - 1024, shX, shH, shW1, shW2, shWp);
    else
        encode_proj_body<14,0>(x_sv, sb1, sb2, conv_b, enc_sv, P_sv, b - 2048, shX, shH, shW1, shW2, shWp);
}

// ---------------- smem layout for conv kernels (floats) ----------------
constexpr int NW     = 24;            // warps per conv block (768 threads)
constexpr int OF_P    = 16512;
constexpr int OF_NORM = 32896;
constexpr int OF_W    = 33408;
constexpr int OF_S    = 34432;
constexpr int SMEM_F1F2 = (OF_S + NW * 4 * 32) * 4;   // 150016 B
constexpr int SMEM_F3   = (OF_W + NW * 32) * 4;       // ~136 KB

// tree argmin over 16 keys: smallest key; ties -> smallest t.
__device__ __forceinline__ void argmin16(const unsigned* ka, unsigned& bk, int& bt)
{
    unsigned tk[8]; int tt[8];
#pragma unroll
    for (int i = 0; i < 8; i++) {
        bool le = ka[2*i] <= ka[2*i+1];
        tk[i] = le ? ka[2*i] : ka[2*i+1];
        tt[i] = le ? 2*i : 2*i+1;
    }
#pragma unroll
    for (int i = 0; i < 4; i++) {
        bool le = tk[2*i] <= tk[2*i+1];
        tk[i] = le ? tk[2*i] : tk[2*i+1];
        tt[i] = le ? tt[2*i] : tt[2*i+1];
    }
#pragma unroll
    for (int i = 0; i < 2; i++) {
        bool le = tk[2*i] <= tk[2*i+1];
        tk[i] = le ? tk[2*i] : tk[2*i+1];
        tt[i] = le ? tt[2*i] : tt[2*i+1];
    }
    bool le = tk[0] <= tk[1];
    bk = le ? tk[0] : tk[1];
    bt = le ? tt[0] : tt[1];
}

// ---------------- edge conv NS=512 (R13 structure: u=2, NW=24) ----------------
// EPI=0 : write outB (=f2) + projB (= f2@Wd + conv_b)
// EPI=1 : mean-pool + MLP head + sigmoid into outF
template<int EPI>
__device__ void conv512_body(
    const float* __restrict__ srcB, const float* __restrict__ dstB,
    const float* __restrict__ PB,   const float* __restrict__ AB,
    float* __restrict__ outB, float* __restrict__ projB,
    const float* __restrict__ conv_W, const float* __restrict__ conv_b,
    const float* __restrict__ oW1, const float* __restrict__ ob1,
    const float* __restrict__ oW2, const float* __restrict__ ob2,
    float* __restrict__ outF, int ev, int out_size,
    float* sh)
{
    float* shT    = sh;
    float* shP    = sh + OF_P;
    float* shNorm = sh + OF_NORM;
    float* shW    = sh + OF_W;       // EPI0: Wd ; EPI1: pool partials
    float* shS    = sh + OF_S;       // EPI0: per-warp staging

    const int tid  = threadIdx.x;
    const int lane = tid & 31;
    const int w    = tid >> 5;           // 0..23

    if (EPI == 0) {
        for (int i = tid; i < 1024; i += 32 * NW)
            shW[i] = conv_W[i] - conv_W[1024 + i];   // Wd
    }
    for (int r = w; r < 512; r += NW) {
        float v = srcB[r * 32 + lane];
        shT[lane * 516 + r] = v;
        shP[r * 32 + lane] = PB[r * 32 + lane];
        float s2 = v * v;
#pragma unroll
        for (int o = 16; o; o >>= 1) s2 += __shfl_xor_sync(FULL, s2, o);
        if (lane == 0) shNorm[r] = s2;
    }
    __syncthreads();

    const float cb = (EPI == 0) ? conv_b[lane] : 0.f;
    float sumv = 0.f;   // EPI1 pooling accumulator (dim = lane)

    for (int pass = 0; pass < 11; pass++) {
        const int g0 = pass * NW + w;
        if (g0 >= 256) break;           // uniform per warp
        const int d0 = g0 * 2;

        float xr[2], a[2];
#pragma unroll
        for (int u = 0; u < 2; u++) {
            xr[u] = dstB[(d0 + u) * 32 + lane];
            a[u]  = AB  [(d0 + u) * 32 + lane];
        }

        // ---- packed f32x2 distance accumulation ----
        u64 acc2[2][8];
#pragma unroll
        for (int u = 0; u < 2; u++)
#pragma unroll
            for (int p = 0; p < 8; p++) acc2[u][p] = 0ull;

#pragma unroll 4
        for (int d = 0; d < 32; d++) {
            u64 xp0 = pack2_dup(__shfl_sync(FULL, xr[0], d));
            u64 xp1 = pack2_dup(__shfl_sync(FULL, xr[1], d));
            const float* base = &shT[d * 516 + 4 * lane];
#pragma unroll
            for (int tp = 0; tp < 4; tp++) {
                ulonglong2 vv = *(const ulonglong2*)(base + 128 * tp);
                acc2[0][2*tp  ] = fma2(xp0, vv.x, acc2[0][2*tp  ]);
                acc2[0][2*tp+1] = fma2(xp0, vv.y, acc2[0][2*tp+1]);
                acc2[1][2*tp  ] = fma2(xp1, vv.x, acc2[1][2*tp  ]);
                acc2[1][2*tp+1] = fma2(xp1, vv.y, acc2[1][2*tp+1]);
            }
        }

        // keys: rv = ||s||^2 - 2<d,s>  (rank-equivalent to d2)
        unsigned karr[2][16];
#pragma unroll
        for (int tp = 0; tp < 4; tp++) {
#pragma unroll
            for (int hh = 0; hh < 2; hh++) {
                int s0 = 4 * lane + 128 * tp + 2 * hh;
                float2 nv = *(const float2*)&shNorm[s0];
                int t0 = 4 * tp + 2 * hh;
#pragma unroll
                for (int u = 0; u < 2; u++) {
                    float2 f = unpack2(acc2[u][2 * tp + hh]);
                    karr[u][t0    ] = sortable_u(fmaf(-2.f, f.x, nv.x));
                    karr[u][t0 + 1] = sortable_u(fmaf(-2.f, f.y, nv.y));
                }
            }
        }

        // ---- top-8 index collection (tree argmin, exact semantics) ----
        int nb0[8], nb1[8];
#pragma unroll
        for (int k = 0; k < 8; k++) {
#pragma unroll
            for (int u = 0; u < 2; u++) {
                unsigned bk; int bt;
                argmin16(karr[u], bk, bt);
                unsigned gk = __reduce_min_sync(FULL, bk);
                int s = 4 * lane + 128 * (bt >> 2) + (bt & 3);
                unsigned cand = (bk == gk) ? (unsigned)s : 0xFFFFFFFFu;
                unsigned gi = __reduce_min_sync(FULL, cand);
                bool won = (bk == gk) && ((unsigned)s == gi);
#pragma unroll
                for (int t = 0; t < 16; t++)
                    karr[u][t] = (won && t == bt) ? 0xFFFFFFFFu : karr[u][t];
                if (u == 0) nb0[k] = (int)gi; else nb1[k] = (int)gi;
            }
        }

        // ---- batched gather + edge activation + max-agg ----
        float m0 = -3.0e38f, m1 = -3.0e38f;
#pragma unroll
        for (int k = 0; k < 8; k++) {
            float pj0 = shP[nb0[k] * 32 + lane];
            float pj1 = shP[nb1[k] * 32 + lane];
            m0 = fmaxf(m0, elu_f(a[0] + pj0));
            m1 = fmaxf(m1, elu_f(a[1] + pj1));
        }

        if (EPI == 0) {
            outB[(d0    ) * 32 + lane] = m0;
            outB[(d0 + 1) * 32 + lane] = m1;
            // fused proj: A_f2 = m @ Wd + conv_b
            shS[(w * 4 + 0) * 32 + lane] = m0;
            shS[(w * 4 + 1) * 32 + lane] = m1;
            __syncwarp();
            float p0 = cb, p1 = cb;
#pragma unroll
            for (int i = 0; i < 32; i++) {
                float wv = shW[i * 32 + lane];
                p0 = fmaf(shS[(w * 4 + 0) * 32 + i], wv, p0);
                p1 = fmaf(shS[(w * 4 + 1) * 32 + i], wv, p1);
            }
            projB[(d0    ) * 32 + lane] = p0;
            projB[(d0 + 1) * 32 + lane] = p1;
            __syncwarp();
        } else {
            sumv += m0 + m1;
        }
    }

    if (EPI == 1) {
        // mean pool over 512 dst + output MLP + sigmoid
        shW[w * 32 + lane] = sumv;   // reuse shW region as pool partials
        __syncthreads();
        if (w == 0) {
            float p = 0.f;
#pragma unroll
            for (int i = 0; i < NW; i++) p += shW[i * 32 + lane];
            p *= (1.f / 512.f);
            float h = ob1[lane];
#pragma unroll
            for (int i = 0; i < 32; i++)
                h = fmaf(__shfl_sync(FULL, p, i), oW1[i * 32 + lane], h);
            h = elu_f(h);
            float z = h * oW2[lane];
#pragma unroll
            for (int o = 16; o; o >>= 1) z += __shfl_xor_sync(FULL, z, o);
            if (lane == 0) {
                float t = z + ob2[0];
                outF[ev] = 1.f / (1.f + __expf(-t));
                if (out_size == 768)
                    ((long long*)(outF + 256))[ev] = (long long)ev;
                else if (out_size > 256 && ev < out_size - 256)
                    outF[256 + ev] = (float)ev;
            }
        }
    }
}

// ---------------- edge conv NS=64 (sv -> trk): u=4, fused proj P_f1 = m@Wb ----------------
__device__ void conv64_body(
    const float* __restrict__ srcB, const float* __restrict__ dstB,
    const float* __restrict__ PB,   const float* __restrict__ AB,
    float* __restrict__ outB, float* __restrict__ projB,
    const float* __restrict__ conv_W,
    float* sh)
{
    constexpr int TS = 65;
    float* shT    = sh;                // [32][65]
    float* shP    = sh + OF_P;         // [64][32]
    float* shNorm = sh + OF_NORM;      // [64]
    float* shW    = sh + OF_W;         // Wb
    float* shS    = sh + OF_S;         // [NW][4][32]

    const int tid  = threadIdx.x;
    const int lane = tid & 31;
    const int w    = tid >> 5;         // 0..23

    for (int i = tid; i < 1024; i += 32 * NW) shW[i] = conv_W[1024 + i];  // Wb
    for (int r = w; r < 64; r += NW) {
        float v = srcB[r * 32 + lane];
        shT[lane * TS + r] = v;
        shP[r * 32 + lane] = PB[r * 32 + lane];
        float s2 = v * v;
#pragma unroll
        for (int o = 16; o; o >>= 1) s2 += __shfl_xor_sync(FULL, s2, o);
        if (lane == 0) shNorm[r] = s2;
    }
    __syncthreads();

    // 128 groups of 4 dst; warp-strided
    for (int g0 = w; g0 < 128; g0 += NW) {
        const int d0 = g0 * 4;

        float xr[4], a[4];
#pragma unroll
        for (int u = 0; u < 4; u++) {
            xr[u] = dstB[(d0 + u) * 32 + lane];
            a[u]  = AB  [(d0 + u) * 32 + lane];
        }

        float acc[4][2];
#pragma unroll
        for (int u = 0; u < 4; u++) { acc[u][0] = 0.f; acc[u][1] = 0.f; }
#pragma unroll 4
        for (int d = 0; d < 32; d++) {
            float xd0 = __shfl_sync(FULL, xr[0], d);
            float xd1 = __shfl_sync(FULL, xr[1], d);
            float xd2 = __shfl_sync(FULL, xr[2], d);
            float xd3 = __shfl_sync(FULL, xr[3], d);
#pragma unroll
            for (int t = 0; t < 2; t++) {
                float v = shT[d * TS + lane + 32 * t];
                acc[0][t] = fmaf(xd0, v, acc[0][t]);
                acc[1][t] = fmaf(xd1, v, acc[1][t]);
                acc[2][t] = fmaf(xd2, v, acc[2][t]);
                acc[3][t] = fmaf(xd3, v, acc[3][t]);
            }
        }
        unsigned karr[4][2];
#pragma unroll
        for (int t = 0; t < 2; t++) {
            float nv = shNorm[lane + 32 * t];
#pragma unroll
            for (int u = 0; u < 4; u++)
                karr[u][t] = sortable_u(fmaf(-2.f, acc[u][t], nv));
        }

        int nb[4][8];
#pragma unroll
        for (int k = 0; k < 8; k++) {
#pragma unroll
            for (int u = 0; u < 4; u++) {
                bool le = karr[u][0] <= karr[u][1];
                unsigned bk = le ? karr[u][0] : karr[u][1];
                int bt = le ? 0 : 1;
                unsigned gk = __reduce_min_sync(FULL, bk);
                int s = lane + 32 * bt;
                unsigned cand = (bk == gk) ? (unsigned)s : 0xFFFFFFFFu;
                unsigned gi = __reduce_min_sync(FULL, cand);
                bool won = (bk == gk) && ((unsigned)s == gi);
#pragma unroll
                for (int t = 0; t < 2; t++)
                    karr[u][t] = (won && t == bt) ? 0xFFFFFFFFu : karr[u][t];
                nb[u][k] = (int)gi;
            }
        }

        float m[4] = {-3.0e38f, -3.0e38f, -3.0e38f, -3.0e38f};
#pragma unroll
        for (int k = 0; k < 8; k++) {
#pragma unroll
            for (int u = 0; u < 4; u++) {
                float pj = shP[nb[u][k] * 32 + lane];
                m[u] = fmaxf(m[u], elu_f(a[u] + pj));
            }
        }

        // write f1 + fused proj P_f1 = m @ Wb
#pragma unroll
        for (int u = 0; u < 4; u++) {
            outB[(d0 + u) * 32 + lane] = m[u];
            shS[(w * 4 + u) * 32 + lane] = m[u];
        }
        __syncwarp();
        float p[4] = {0.f, 0.f, 0.f, 0.f};
#pragma unroll
        for (int i = 0; i < 32; i++) {
            float wv = shW[i * 32 + lane];
#pragma unroll
            for (int u = 0; u < 4; u++)
                p[u] = fmaf(shS[(w * 4 + u) * 32 + i], wv, p[u]);
        }
#pragma unroll
        for (int u = 0; u < 4; u++) projB[(d0 + u) * 32 + lane] = p[u];
        __syncwarp();
    }
}

// merged conv for f1 (sv->trk, NS=64, +P_f1) and f2 (pfc->trk, NS=512, +A_f2).
// Interleaved block order: even = f2 (long), odd = f1 (short) for wave mixing.
__global__ void __launch_bounds__(32 * NW, 1) conv_f1f2_k(
    const float* __restrict__ enc_sv,  const float* __restrict__ enc_pfc,
    const float* __restrict__ enc_trk,
    const float* __restrict__ P_sv,    const float* __restrict__ P_pfc,
    const float* __restrict__ A_trk,
    const float* __restrict__ conv_W,  const float* __restrict__ conv_b,
    float* __restrict__ f1, float* __restrict__ f2,
    float* __restrict__ P_f1, float* __restrict__ A_f2)
{
    extern __shared__ float sh[];
    int b = blockIdx.x;
    int e = b >> 1;
    if ((b & 1) == 0) {
        conv512_body<0>(enc_pfc + (size_t)e * 512 * 32,
                        enc_trk + (size_t)e * 512 * 32,
                        P_pfc   + (size_t)e * 512 * 32,
                        A_trk   + (size_t)e * 512 * 32,
                        f2      + (size_t)e * 512 * 32,
                        A_f2    + (size_t)e * 512 * 32,
                        conv_W, conv_b,
                        nullptr, nullptr, nullptr, nullptr, nullptr, 0, 0, sh);
    } else {
        conv64_body(enc_sv  + (size_t)e * 64  * 32,
                    enc_trk + (size_t)e * 512 * 32,
                    P_sv    + (size_t)e * 64  * 32,
                    A_trk   + (size_t)e * 512 * 32,
                    f1      + (size_t)e * 512 * 32,
                    P_f1    + (size_t)e * 512 * 32,
                    conv_W, sh);
    }
}

// conv f3 + fused mean-pool + output MLP + sigmoid (+ arange tail)
__global__ void __launch_bounds__(32 * NW, 1) conv_f3_k(
    const float* __restrict__ f1, const float* __restrict__ f2,
    const float* __restrict__ P_f1, const float* __restrict__ A_f2,
    const float* __restrict__ oW1, const float* __restrict__ ob1,
    const float* __restrict__ oW2, const float* __restrict__ ob2,
    float* __restrict__ outF, int out_size)
{
    extern __shared__ float sh[];
    int b = blockIdx.x;
    conv512_body<1>(f1   + (size_t)b * 512 * 32,
                    f2   + (size_t)b * 512 * 32,
                    P_f1 + (size_t)b * 512 * 32,
                    A_f2 + (size_t)b * 512 * 32,
                    nullptr, nullptr, nullptr, nullptr,
                    oW1, ob1, oW2, ob2, outF, b, out_size, sh);
}

} // namespace

extern "C" void kernel_launch(void* const* d_in, const int* in_sizes, int n_in,
                              void* d_out, int out_size)
{
    const float* x_sv   = (const float*)d_in[0];
    const float* x_trk  = (const float*)d_in[1];
    const float* x_pfc  = (const float*)d_in[2];
    // d_in[3..5] = batch indices (implicit, unused)
    const float* sv_W1  = (const float*)d_in[6];
    const float* sv_b1  = (const float*)d_in[7];
    const float* sv_W2  = (const float*)d_in[8];
    const float* sv_b2  = (const float*)d_in[9];
    const float* trk_W1 = (const float*)d_in[10];
    const float* trk_b1 = (const float*)d_in[11];
    const float* trk_W2 = (const float*)d_in[12];
    const float* trk_b2 = (const float*)d_in[13];
    const float* pfc_W1 = (const float*)d_in[14];
    const float* pfc_b1 = (const float*)d_in[15];
    const float* pfc_W2 = (const float*)d_in[16];
    const float* pfc_b2 = (const float*)d_in[17];
    const float* conv_W = (const float*)d_in[18];
    const float* conv_b = (const float*)d_in[19];
    const float* out_W1 = (const float*)d_in[20];
    const float* out_b1 = (const float*)d_in[21];
    const float* out_W2 = (const float*)d_in[22];
    const float* out_b2 = (const float*)d_in[23];

    float *enc_sv, *enc_trk, *enc_pfc, *f1, *f2;
    float *P_sv, *P_pfc, *P_f1, *A_trk, *A_f2;
    cudaGetSymbolAddress((void**)&enc_sv,  g_enc_sv);
    cudaGetSymbolAddress((void**)&enc_trk, g_enc_trk);
    cudaGetSymbolAddress((void**)&enc_pfc, g_enc_pfc);
    cudaGetSymbolAddress((void**)&f1, g_f1);
    cudaGetSymbolAddress((void**)&f2, g_f2);
    cudaGetSymbolAddress((void**)&P_sv,  g_P_sv);
    cudaGetSymbolAddress((void**)&P_pfc, g_P_pfc);
    cudaGetSymbolAddress((void**)&P_f1,  g_P_f1);
    cudaGetSymbolAddress((void**)&A_trk, g_A_trk);
    cudaGetSymbolAddress((void**)&A_f2,  g_A_f2);

    cudaFuncSetAttribute(conv_f1f2_k,
                         cudaFuncAttributeMaxDynamicSharedMemorySize, SMEM_F1F2);
    cudaFuncSetAttribute(conv_f3_k,
                         cudaFuncAttributeMaxDynamicSharedMemorySize, SMEM_F3);

    encode_all_k<<<2176, 256>>>(
        x_trk, trk_W1, trk_b1, trk_W2, trk_b2,
        x_pfc, pfc_W1, pfc_b1, pfc_W2, pfc_b2,
        x_sv,  sv_W1,  sv_b1,  sv_W2,  sv_b2,
        conv_W, conv_b,
        enc_trk, enc_pfc, enc_sv, A_trk, P_pfc, P_sv);

    conv_f1f2_k<<<512, 32 * NW, SMEM_F1F2>>>(enc_sv, enc_pfc, enc_trk,
                                             P_sv, P_pfc, A_trk,
                                             conv_W, conv_b,
                                             f1, f2, P_f1, A_f2);

    conv_f3_k<<<BQ, 32 * NW, SMEM_F3>>>(f1, f2, P_f1, A_f2,
                                        out_W1, out_b1, out_W2, out_b2,
                                        (float*)d_out, out_size);
}

// round 17
// speedup vs baseline: 1.6460x; 1.1178x over previous
#include <cuda_runtime.h>
#include <math.h>

namespace {

constexpr int BQ   = 256;
constexpr int NSV  = 64;
constexpr int NTRK = 512;
constexpr int H    = 32;
constexpr unsigned FULL = 0xffffffffu;
typedef unsigned long long u64;

// ---------------- scratch (static device globals; no allocation) ----------------
__device__ float g_enc_sv [BQ * NSV  * H];
__device__ float g_enc_trk[BQ * NTRK * H];
__device__ float g_enc_pfc[BQ * NTRK * H];
__device__ float g_f1[BQ * NTRK * H];
__device__ float g_f2[BQ * NTRK * H];
__device__ float g_P_sv [BQ * NSV  * H];   // enc_sv  @ Wb
__device__ float g_P_pfc[BQ * NTRK * H];   // enc_pfc @ Wb
__device__ float g_P_f1 [BQ * NTRK * H];   // f1      @ Wb
__device__ float g_A_trk[BQ * NTRK * H];   // enc_trk @ Wd + b
__device__ float g_A_f2 [BQ * NTRK * H];   // f2      @ Wd + b

__device__ __forceinline__ float elu_f(float x) {
    return x > 0.f ? x : (__expf(x) - 1.f);
}

// monotone float -> sortable uint
__device__ __forceinline__ unsigned sortable_u(float v) {
    unsigned u = __float_as_uint(v);
    return (u & 0x80000000u) ? ~u : (u | 0x80000000u);
}

// packed fp32x2 helpers (Blackwell)
__device__ __forceinline__ u64 pack2_dup(float v) {
    u64 r; asm("mov.b64 %0, {%1, %1};" : "=l"(r) : "f"(v)); return r;
}
__device__ __forceinline__ u64 fma2(u64 a, u64 b, u64 c) {
    u64 d; asm("fma.rn.f32x2 %0, %1, %2, %3;" : "=l"(d) : "l"(a), "l"(b), "l"(c)); return d;
}
__device__ __forceinline__ float2 unpack2(u64 v) {
    float2 f; asm("mov.b64 {%0, %1}, %2;" : "=f"(f.x), "=f"(f.y) : "l"(v)); return f;
}

// ---------------- encoder + fused node projection (u=8 nodes/warp/iter) ----------------
template<int FIN, int MODE>
__device__ __forceinline__ void encode_proj_body(
    const float* __restrict__ x,
    const float* __restrict__ b1, const float* __restrict__ b2,
    const float* __restrict__ conv_b,
    float* __restrict__ out, float* __restrict__ projOut, int blk,
    float (*shX)[240], float (*shH)[8][32],
    const float* shW1, const float* shW2, const float* shWp)
{
    int tid = threadIdx.x, lane = tid & 31, w = tid >> 5;

    const float bb1 = b1[lane], bb2 = b2[lane];
    const float bp  = MODE ? conv_b[lane] : 0.f;

    int base = (blk * 8 + w) * 16;
#pragma unroll
    for (int it = 0; it < 2; it++) {
        int n0 = base + it * 8;
        for (int i = lane; i < 8 * FIN; i += 32) shX[w][i] = x[n0 * FIN + i];
        __syncwarp();
        float h[8];
#pragma unroll
        for (int u = 0; u < 8; u++) h[u] = bb1;
#pragma unroll
        for (int i = 0; i < FIN; i++) {
            float wv = shW1[i * 32 + lane];
#pragma unroll
            for (int u = 0; u < 8; u++)
                h[u] = fmaf(shX[w][u * FIN + i], wv, h[u]);
        }
#pragma unroll
        for (int u = 0; u < 8; u++) { h[u] = elu_f(h[u]); shH[w][u][lane] = h[u]; }
        __syncwarp();
        float y[8];
#pragma unroll
        for (int u = 0; u < 8; u++) y[u] = bb2;
#pragma unroll
        for (int i = 0; i < 32; i++) {
            float wv = shW2[i * 32 + lane];
#pragma unroll
            for (int u = 0; u < 8; u++)
                y[u] = fmaf(shH[w][u][i], wv, y[u]);
        }
        __syncwarp();
#pragma unroll
        for (int u = 0; u < 8; u++) {
            float yv = elu_f(y[u]);
            out[(n0 + u) * 32 + lane] = yv;
            shH[w][u][lane] = yv;
        }
        __syncwarp();
        float p[8];
#pragma unroll
        for (int u = 0; u < 8; u++) p[u] = bp;
#pragma unroll
        for (int i = 0; i < 32; i++) {
            float wv = shWp[i * 32 + lane];
#pragma unroll
            for (int u = 0; u < 8; u++)
                p[u] = fmaf(shH[w][u][i], wv, p[u]);
        }
#pragma unroll
        for (int u = 0; u < 8; u++) projOut[(n0 + u) * 32 + lane] = p[u];
        __syncwarp();
    }
}

// merged encoder+proj1
__global__ void __launch_bounds__(256) encode_all_k(
    const float* __restrict__ x_trk, const float* __restrict__ tW1, const float* __restrict__ tb1,
    const float* __restrict__ tW2, const float* __restrict__ tb2,
    const float* __restrict__ x_pfc, const float* __restrict__ pW1, const float* __restrict__ pb1,
    const float* __restrict__ pW2, const float* __restrict__ pb2,
    const float* __restrict__ x_sv, const float* __restrict__ sW1, const float* __restrict__ sb1,
    const float* __restrict__ sW2, const float* __restrict__ sb2,
    const float* __restrict__ conv_W, const float* __restrict__ conv_b,
    float* __restrict__ enc_trk, float* __restrict__ enc_pfc, float* __restrict__ enc_sv,
    float* __restrict__ A_trk, float* __restrict__ P_pfc, float* __restrict__ P_sv)
{
    __shared__ float shX[8][240];
    __shared__ float shH[8][8][32];
    __shared__ float shW1[960];
    __shared__ float shW2[1024];
    __shared__ float shWp[1024];
    int b = blockIdx.x;
    const float* W1 = (b < 1024) ? tW1 : (b < 2048) ? pW1 : sW1;
    const float* W2 = (b < 1024) ? tW2 : (b < 2048) ? pW2 : sW2;
    const int fin   = (b < 1024) ? 30 : (b < 2048) ? 10 : 14;
    for (int i = threadIdx.x; i < fin * 32; i += 256) shW1[i] = W1[i];
    for (int i = threadIdx.x; i < 1024; i += 256) shW2[i] = W2[i];
    if (b < 1024) {
        for (int i = threadIdx.x; i < 1024; i += 256)
            shWp[i] = conv_W[i] - conv_W[1024 + i];         // Wd
    } else {
        for (int i = threadIdx.x; i < 1024; i += 256)
            shWp[i] = conv_W[1024 + i];                     // Wb
    }
    __syncthreads();
    if (b < 1024)
        encode_proj_body<30,1>(x_trk, tb1, tb2, conv_b, enc_trk, A_trk, b, shX, shH, shW1, shW2, shWp);
    else if (b < 2048)
        encode_proj_body<10,0>(x_pfc, pb1, pb2, conv_b, enc_pfc, P_pfc, b - 1024, shX, shH, shW1, shW2, shWp);
    else
        encode_proj_body<14,0>(x_sv, sb1, sb2, conv_b, enc_sv, P_sv, b - 2048, shX, shH, shW1, shW2, shWp);
}

// ---------------- smem layout for conv kernels (floats) ----------------
constexpr int NW     = 24;            // warps per conv block (768 threads)
constexpr int OF_P    = 16512;
constexpr int OF_NORM = 32896;
constexpr int OF_W    = 33408;
constexpr int OF_S    = 34432;
constexpr int SMEM_F1F2 = (OF_S + NW * 4 * 32) * 4;   // 150016 B
constexpr int SMEM_F3   = (OF_W + NW * 32) * 4;       // ~136 KB

// tree argmin over 16 keys: smallest key; ties -> smallest t.
__device__ __forceinline__ void argmin16(const unsigned* ka, unsigned& bk, int& bt)
{
    unsigned tk[8]; int tt[8];
#pragma unroll
    for (int i = 0; i < 8; i++) {
        bool le = ka[2*i] <= ka[2*i+1];
        tk[i] = le ? ka[2*i] : ka[2*i+1];
        tt[i] = le ? 2*i : 2*i+1;
    }
#pragma unroll
    for (int i = 0; i < 4; i++) {
        bool le = tk[2*i] <= tk[2*i+1];
        tk[i] = le ? tk[2*i] : tk[2*i+1];
        tt[i] = le ? tt[2*i] : tt[2*i+1];
    }
#pragma unroll
    for (int i = 0; i < 2; i++) {
        bool le = tk[2*i] <= tk[2*i+1];
        tk[i] = le ? tk[2*i] : tk[2*i+1];
        tt[i] = le ? tt[2*i] : tt[2*i+1];
    }
    bool le = tk[0] <= tk[1];
    bk = le ? tk[0] : tk[1];
    bt = le ? tt[0] : tt[1];
}

// ---------------- edge conv NS=512 (R13 structure: u=2, NW=24) ----------------
// EPI=0 : write outB (=f2) + projB (= f2@Wd + conv_b)
// EPI=1 : mean-pool + MLP head + sigmoid into outF
template<int EPI>
__device__ void conv512_body(
    const float* __restrict__ srcB, const float* __restrict__ dstB,
    const float* __restrict__ PB,   const float* __restrict__ AB,
    float* __restrict__ outB, float* __restrict__ projB,
    const float* __restrict__ conv_W, const float* __restrict__ conv_b,
    const float* __restrict__ oW1, const float* __restrict__ ob1,
    const float* __restrict__ oW2, const float* __restrict__ ob2,
    float* __restrict__ outF, int ev, int out_size,
    float* sh)
{
    float* shT    = sh;
    float* shP    = sh + OF_P;
    float* shNorm = sh + OF_NORM;
    float* shW    = sh + OF_W;       // EPI0: Wd ; EPI1: pool partials
    float* shS    = sh + OF_S;       // EPI0: per-warp staging

    const int tid  = threadIdx.x;
    const int lane = tid & 31;
    const int w    = tid >> 5;           // 0..23

    if (EPI == 0) {
        for (int i = tid; i < 1024; i += 32 * NW)
            shW[i] = conv_W[i] - conv_W[1024 + i];   // Wd
    }
    for (int r = w; r < 512; r += NW) {
        float v = srcB[r * 32 + lane];
        shT[lane * 516 + r] = v;
        shP[r * 32 + lane] = PB[r * 32 + lane];
        float s2 = v * v;
#pragma unroll
        for (int o = 16; o; o >>= 1) s2 += __shfl_xor_sync(FULL, s2, o);
        if (lane == 0) shNorm[r] = s2;
    }
    __syncthreads();

    const float cb = (EPI == 0) ? conv_b[lane] : 0.f;
    float sumv = 0.f;   // EPI1 pooling accumulator (dim = lane)

    for (int pass = 0; pass < 11; pass++) {
        const int g0 = pass * NW + w;
        if (g0 >= 256) break;           // uniform per warp
        const int d0 = g0 * 2;

        float xr[2], a[2];
#pragma unroll
        for (int u = 0; u < 2; u++) {
            xr[u] = dstB[(d0 + u) * 32 + lane];
            a[u]  = AB  [(d0 + u) * 32 + lane];
        }

        // ---- packed f32x2 distance accumulation ----
        u64 acc2[2][8];
#pragma unroll
        for (int u = 0; u < 2; u++)
#pragma unroll
            for (int p = 0; p < 8; p++) acc2[u][p] = 0ull;

#pragma unroll 4
        for (int d = 0; d < 32; d++) {
            u64 xp0 = pack2_dup(__shfl_sync(FULL, xr[0], d));
            u64 xp1 = pack2_dup(__shfl_sync(FULL, xr[1], d));
            const float* base = &shT[d * 516 + 4 * lane];
#pragma unroll
            for (int tp = 0; tp < 4; tp++) {
                ulonglong2 vv = *(const ulonglong2*)(base + 128 * tp);
                acc2[0][2*tp  ] = fma2(xp0, vv.x, acc2[0][2*tp  ]);
                acc2[0][2*tp+1] = fma2(xp0, vv.y, acc2[0][2*tp+1]);
                acc2[1][2*tp  ] = fma2(xp1, vv.x, acc2[1][2*tp  ]);
                acc2[1][2*tp+1] = fma2(xp1, vv.y, acc2[1][2*tp+1]);
            }
        }

        // keys: rv = ||s||^2 - 2<d,s>  (rank-equivalent to d2)
        unsigned karr[2][16];
#pragma unroll
        for (int tp = 0; tp < 4; tp++) {
#pragma unroll
            for (int hh = 0; hh < 2; hh++) {
                int s0 = 4 * lane + 128 * tp + 2 * hh;
                float2 nv = *(const float2*)&shNorm[s0];
                int t0 = 4 * tp + 2 * hh;
#pragma unroll
                for (int u = 0; u < 2; u++) {
                    float2 f = unpack2(acc2[u][2 * tp + hh]);
                    karr[u][t0    ] = sortable_u(fmaf(-2.f, f.x, nv.x));
                    karr[u][t0 + 1] = sortable_u(fmaf(-2.f, f.y, nv.y));
                }
            }
        }

        // ---- top-8 index collection (tree argmin, exact semantics) ----
        int nb0[8], nb1[8];
#pragma unroll
        for (int k = 0; k < 8; k++) {
#pragma unroll
            for (int u = 0; u < 2; u++) {
                unsigned bk; int bt;
                argmin16(karr[u], bk, bt);
                unsigned gk = __reduce_min_sync(FULL, bk);
                int s = 4 * lane + 128 * (bt >> 2) + (bt & 3);
                unsigned cand = (bk == gk) ? (unsigned)s : 0xFFFFFFFFu;
                unsigned gi = __reduce_min_sync(FULL, cand);
                bool won = (bk == gk) && ((unsigned)s == gi);
#pragma unroll
                for (int t = 0; t < 16; t++)
                    karr[u][t] = (won && t == bt) ? 0xFFFFFFFFu : karr[u][t];
                if (u == 0) nb0[k] = (int)gi; else nb1[k] = (int)gi;
            }
        }

        // ---- batched gather + edge activation + max-agg ----
        float m0 = -3.0e38f, m1 = -3.0e38f;
#pragma unroll
        for (int k = 0; k < 8; k++) {
            float pj0 = shP[nb0[k] * 32 + lane];
            float pj1 = shP[nb1[k] * 32 + lane];
            m0 = fmaxf(m0, elu_f(a[0] + pj0));
            m1 = fmaxf(m1, elu_f(a[1] + pj1));
        }

        if (EPI == 0) {
            outB[(d0    ) * 32 + lane] = m0;
            outB[(d0 + 1) * 32 + lane] = m1;
            // fused proj: A_f2 = m @ Wd + conv_b
            shS[(w * 4 + 0) * 32 + lane] = m0;
            shS[(w * 4 + 1) * 32 + lane] = m1;
            __syncwarp();
            float p0 = cb, p1 = cb;
#pragma unroll
            for (int i = 0; i < 32; i++) {
                float wv = shW[i * 32 + lane];
                p0 = fmaf(shS[(w * 4 + 0) * 32 + i], wv, p0);
                p1 = fmaf(shS[(w * 4 + 1) * 32 + i], wv, p1);
            }
            projB[(d0    ) * 32 + lane] = p0;
            projB[(d0 + 1) * 32 + lane] = p1;
            __syncwarp();
        } else {
            sumv += m0 + m1;
        }
    }

    if (EPI == 1) {
        // mean pool over 512 dst + output MLP + sigmoid
        shW[w * 32 + lane] = sumv;   // reuse shW region as pool partials
        __syncthreads();
        if (w == 0) {
            float p = 0.f;
#pragma unroll
            for (int i = 0; i < NW; i++) p += shW[i * 32 + lane];
            p *= (1.f / 512.f);
            float h = ob1[lane];
#pragma unroll
            for (int i = 0; i < 32; i++)
                h = fmaf(__shfl_sync(FULL, p, i), oW1[i * 32 + lane], h);
            h = elu_f(h);
            float z = h * oW2[lane];
#pragma unroll
            for (int o = 16; o; o >>= 1) z += __shfl_xor_sync(FULL, z, o);
            if (lane == 0) {
                float t = z + ob2[0];
                outF[ev] = 1.f / (1.f + __expf(-t));
                if (out_size == 768)
                    ((long long*)(outF + 256))[ev] = (long long)ev;
                else if (out_size > 256 && ev < out_size - 256)
                    outF[256 + ev] = (float)ev;
            }
        }
    }
}

// ---------------- edge conv NS=64 (sv -> trk): u=4, fused proj P_f1 = m@Wb ----------------
__device__ void conv64_body(
    const float* __restrict__ srcB, const float* __restrict__ dstB,
    const float* __restrict__ PB,   const float* __restrict__ AB,
    float* __restrict__ outB, float* __restrict__ projB,
    const float* __restrict__ conv_W,
    float* sh)
{
    constexpr int TS = 65;
    float* shT    = sh;                // [32][65]
    float* shP    = sh + OF_P;         // [64][32]
    float* shNorm = sh + OF_NORM;      // [64]
    float* shW    = sh + OF_W;         // Wb
    float* shS    = sh + OF_S;         // [NW][4][32]

    const int tid  = threadIdx.x;
    const int lane = tid & 31;
    const int w    = tid >> 5;         // 0..23

    for (int i = tid; i < 1024; i += 32 * NW) shW[i] = conv_W[1024 + i];  // Wb
    for (int r = w; r < 64; r += NW) {
        float v = srcB[r * 32 + lane];
        shT[lane * TS + r] = v;
        shP[r * 32 + lane] = PB[r * 32 + lane];
        float s2 = v * v;
#pragma unroll
        for (int o = 16; o; o >>= 1) s2 += __shfl_xor_sync(FULL, s2, o);
        if (lane == 0) shNorm[r] = s2;
    }
    __syncthreads();

    // 128 groups of 4 dst; warp-strided
    for (int g0 = w; g0 < 128; g0 += NW) {
        const int d0 = g0 * 4;

        float xr[4], a[4];
#pragma unroll
        for (int u = 0; u < 4; u++) {
            xr[u] = dstB[(d0 + u) * 32 + lane];
            a[u]  = AB  [(d0 + u) * 32 + lane];
        }

        float acc[4][2];
#pragma unroll
        for (int u = 0; u < 4; u++) { acc[u][0] = 0.f; acc[u][1] = 0.f; }
#pragma unroll 4
        for (int d = 0; d < 32; d++) {
            float xd0 = __shfl_sync(FULL, xr[0], d);
            float xd1 = __shfl_sync(FULL, xr[1], d);
            float xd2 = __shfl_sync(FULL, xr[2], d);
            float xd3 = __shfl_sync(FULL, xr[3], d);
#pragma unroll
            for (int t = 0; t < 2; t++) {
                float v = shT[d * TS + lane + 32 * t];
                acc[0][t] = fmaf(xd0, v, acc[0][t]);
                acc[1][t] = fmaf(xd1, v, acc[1][t]);
                acc[2][t] = fmaf(xd2, v, acc[2][t]);
                acc[3][t] = fmaf(xd3, v, acc[3][t]);
            }
        }
        unsigned karr[4][2];
#pragma unroll
        for (int t = 0; t < 2; t++) {
            float nv = shNorm[lane + 32 * t];
#pragma unroll
            for (int u = 0; u < 4; u++)
                karr[u][t] = sortable_u(fmaf(-2.f, acc[u][t], nv));
        }

        int nb[4][8];
#pragma unroll
        for (int k = 0; k < 8; k++) {
#pragma unroll
            for (int u = 0; u < 4; u++) {
                bool le = karr[u][0] <= karr[u][1];
                unsigned bk = le ? karr[u][0] : karr[u][1];
                int bt = le ? 0 : 1;
                unsigned gk = __reduce_min_sync(FULL, bk);
                int s = lane + 32 * bt;
                unsigned cand = (bk == gk) ? (unsigned)s : 0xFFFFFFFFu;
                unsigned gi = __reduce_min_sync(FULL, cand);
                bool won = (bk == gk) && ((unsigned)s == gi);
#pragma unroll
                for (int t = 0; t < 2; t++)
                    karr[u][t] = (won && t == bt) ? 0xFFFFFFFFu : karr[u][t];
                nb[u][k] = (int)gi;
            }
        }

        float m[4] = {-3.0e38f, -3.0e38f, -3.0e38f, -3.0e38f};
#pragma unroll
        for (int k = 0; k < 8; k++) {
#pragma unroll
            for (int u = 0; u < 4; u++) {
                float pj = shP[nb[u][k] * 32 + lane];
                m[u] = fmaxf(m[u], elu_f(a[u] + pj));
            }
        }

        // write f1 + fused proj P_f1 = m @ Wb
#pragma unroll
        for (int u = 0; u < 4; u++) {
            outB[(d0 + u) * 32 + lane] = m[u];
            shS[(w * 4 + u) * 32 + lane] = m[u];
        }
        __syncwarp();
        float p[4] = {0.f, 0.f, 0.f, 0.f};
#pragma unroll
        for (int i = 0; i < 32; i++) {
            float wv = shW[i * 32 + lane];
#pragma unroll
            for (int u = 0; u < 4; u++)
                p[u] = fmaf(shS[(w * 4 + u) * 32 + i], wv, p[u]);
        }
#pragma unroll
        for (int u = 0; u < 4; u++) projB[(d0 + u) * 32 + lane] = p[u];
        __syncwarp();
    }
}

// merged conv for f1 (sv->trk, NS=64, +P_f1) and f2 (pfc->trk, NS=512, +A_f2).
// R13 ordering: long f2 blocks first, short f1 blocks backfill the tail.
__global__ void __launch_bounds__(32 * NW, 1) conv_f1f2_k(
    const float* __restrict__ enc_sv,  const float* __restrict__ enc_pfc,
    const float* __restrict__ enc_trk,
    const float* __restrict__ P_sv,    const float* __restrict__ P_pfc,
    const float* __restrict__ A_trk,
    const float* __restrict__ conv_W,  const float* __restrict__ conv_b,
    float* __restrict__ f1, float* __restrict__ f2,
    float* __restrict__ P_f1, float* __restrict__ A_f2)
{
    extern __shared__ float sh[];
    int b = blockIdx.x;
    if (b < 256) {
        conv512_body<0>(enc_pfc + (size_t)b * 512 * 32,
                        enc_trk + (size_t)b * 512 * 32,
                        P_pfc   + (size_t)b * 512 * 32,
                        A_trk   + (size_t)b * 512 * 32,
                        f2      + (size_t)b * 512 * 32,
                        A_f2    + (size_t)b * 512 * 32,
                        conv_W, conv_b,
                        nullptr, nullptr, nullptr, nullptr, nullptr, 0, 0, sh);
    } else {
        int e = b - 256;
        conv64_body(enc_sv  + (size_t)e * 64  * 32,
                    enc_trk + (size_t)e * 512 * 32,
                    P_sv    + (size_t)e * 64  * 32,
                    A_trk   + (size_t)e * 512 * 32,
                    f1      + (size_t)e * 512 * 32,
                    P_f1    + (size_t)e * 512 * 32,
                    conv_W, sh);
    }
}

// conv f3 + fused mean-pool + output MLP + sigmoid (+ arange tail)
__global__ void __launch_bounds__(32 * NW, 1) conv_f3_k(
    const float* __restrict__ f1, const float* __restrict__ f2,
    const float* __restrict__ P_f1, const float* __restrict__ A_f2,
    const float* __restrict__ oW1, const float* __restrict__ ob1,
    const float* __restrict__ oW2, const float* __restrict__ ob2,
    float* __restrict__ outF, int out_size)
{
    extern __shared__ float sh[];
    int b = blockIdx.x;
    conv512_body<1>(f1   + (size_t)b * 512 * 32,
                    f2   + (size_t)b * 512 * 32,
                    P_f1 + (size_t)b * 512 * 32,
                    A_f2 + (size_t)b * 512 * 32,
                    nullptr, nullptr, nullptr, nullptr,
                    oW1, ob1, oW2, ob2, outF, b, out_size, sh);
}

} // namespace

extern "C" void kernel_launch(void* const* d_in, const int* in_sizes, int n_in,
                              void* d_out, int out_size)
{
    const float* x_sv   = (const float*)d_in[0];
    const float* x_trk  = (const float*)d_in[1];
    const float* x_pfc  = (const float*)d_in[2];
    // d_in[3..5] = batch indices (implicit, unused)
    const float* sv_W1  = (const float*)d_in[6];
    const float* sv_b1  = (const float*)d_in[7];
    const float* sv_W2  = (const float*)d_in[8];
    const float* sv_b2  = (const float*)d_in[9];
    const float* trk_W1 = (const float*)d_in[10];
    const float* trk_b1 = (const float*)d_in[11];
    const float* trk_W2 = (const float*)d_in[12];
    const float* trk_b2 = (const float*)d_in[13];
    const float* pfc_W1 = (const float*)d_in[14];
    const float* pfc_b1 = (const float*)d_in[15];
    const float* pfc_W2 = (const float*)d_in[16];
    const float* pfc_b2 = (const float*)d_in[17];
    const float* conv_W = (const float*)d_in[18];
    const float* conv_b = (const float*)d_in[19];
    const float* out_W1 = (const float*)d_in[20];
    const float* out_b1 = (const float*)d_in[21];
    const float* out_W2 = (const float*)d_in[22];
    const float* out_b2 = (const float*)d_in[23];

    float *enc_sv, *enc_trk, *enc_pfc, *f1, *f2;
    float *P_sv, *P_pfc, *P_f1, *A_trk, *A_f2;
    cudaGetSymbolAddress((void**)&enc_sv,  g_enc_sv);
    cudaGetSymbolAddress((void**)&enc_trk, g_enc_trk);
    cudaGetSymbolAddress((void**)&enc_pfc, g_enc_pfc);
    cudaGetSymbolAddress((void**)&f1, g_f1);
    cudaGetSymbolAddress((void**)&f2, g_f2);
    cudaGetSymbolAddress((void**)&P_sv,  g_P_sv);
    cudaGetSymbolAddress((void**)&P_pfc, g_P_pfc);
    cudaGetSymbolAddress((void**)&P_f1,  g_P_f1);
    cudaGetSymbolAddress((void**)&A_trk, g_A_trk);
    cudaGetSymbolAddress((void**)&A_f2,  g_A_f2);

    cudaFuncSetAttribute(conv_f1f2_k,
                         cudaFuncAttributeMaxDynamicSharedMemorySize, SMEM_F1F2);
    cudaFuncSetAttribute(conv_f3_k,
                         cudaFuncAttributeMaxDynamicSharedMemorySize, SMEM_F3);

    encode_all_k<<<2176, 256>>>(
        x_trk, trk_W1, trk_b1, trk_W2, trk_b2,
        x_pfc, pfc_W1, pfc_b1, pfc_W2, pfc_b2,
        x_sv,  sv_W1,  sv_b1,  sv_W2,  sv_b2,
        conv_W, conv_b,
        enc_trk, enc_pfc, enc_sv, A_trk, P_pfc, P_sv);

    conv_f1f2_k<<<512, 32 * NW, SMEM_F1F2>>>(enc_sv, enc_pfc, enc_trk,
                                             P_sv, P_pfc, A_trk,
                                             conv_W, conv_b,
                                             f1, f2, P_f1, A_f2);

    conv_f3_k<<<BQ, 32 * NW, SMEM_F3>>>(f1, f2, P_f1, A_f2,
                                        out_W1, out_b1, out_W2, out_b2,
                                        (float*)d_out, out_size);
}